// round 2
// baseline (speedup 1.0000x reference)
#include <cuda_runtime.h>

// ---------------- problem constants ----------------
#define BB    16
#define CIN   512
#define COUT  512
#define SDIM  512
#define HI    32
#define WI    32
#define HO    64
#define WO    64
#define PADW  66                 // 64 + 1 halo each side
#define PLANE (PADW * PADW)      // 4356

#define LIN_SCALE  0.04419417382415922f     // 1/sqrt(512)
#define CONV_SCALE 0.014731391274719742f    // 1/sqrt(512*9)
#define ACT_GAIN   1.4142135623730951f
#define NEG_SLOPE  0.2f
#define EPS_DEMOD  1e-8f

// ---------------- device scratch (static: no allocations allowed) ----------
__device__ float g_s[BB * CIN];                       // style
__device__ float g_demod[BB * COUT];                  // demod factors
__device__ float g_wt[9 * COUT * CIN];                // tap-major scaled weights
__device__ float g_wsq[COUT * CIN];                   // sum_kl w^2
__device__ float g_xm[(size_t)BB * CIN * PLANE];      // padded modulated upsample (~136MB)

// ---------------- kernel 1: style = EqualLinear(w) -------------------------
__global__ void style_kernel(const float* __restrict__ w,
                             const float* __restrict__ lin_w,
                             const float* __restrict__ lin_b)
{
    const int b = blockIdx.x;
    const int i = threadIdx.x;            // 512 threads, one output channel each
    __shared__ float ws[SDIM];
    ws[i] = w[b * SDIM + i];
    __syncthreads();
    const float* lw = lin_w + (size_t)i * SDIM;
    float acc = 0.f;
#pragma unroll 8
    for (int j = 0; j < SDIM; ++j)
        acc = fmaf(ws[j], lw[j], acc);
    g_s[b * CIN + i] = acc * LIN_SCALE + lin_b[i];
}

// ---------------- kernel 2: weight transpose (tap-major) + sum-of-squares --
__global__ void wprep_kernel(const float* __restrict__ conv_w)
{
    const int o = blockIdx.x;             // 512
    const int i = threadIdx.x;            // 512
    const float* wp = conv_w + ((size_t)o * CIN + i) * 9;
    float q = 0.f;
#pragma unroll
    for (int kk = 0; kk < 9; ++kk) {
        const float v = wp[kk] * CONV_SCALE;
        g_wt[(size_t)kk * COUT * CIN + o * CIN + i] = v;
        q = fmaf(v, v, q);
    }
    g_wsq[o * CIN + i] = q;
}

// ---------------- kernel 3: demod[b][o] = rsqrt(wsq @ s^2 + eps) -----------
__global__ void demod_kernel()
{
    const int b = blockIdx.x;             // 16
    const int o = threadIdx.x;            // 512
    __shared__ float s2[CIN];
    const float sv = g_s[b * CIN + o];
    s2[o] = sv * sv;
    __syncthreads();
    const float* wq = g_wsq + (size_t)o * CIN;
    float acc = 0.f;
#pragma unroll 8
    for (int i = 0; i < CIN; ++i)
        acc = fmaf(wq[i], s2[i], acc);
    g_demod[b * COUT + o] = rsqrtf(acc + EPS_DEMOD);
}

// ---------------- kernel 4: bilinear 2x upsample * style, zero-padded ------
__global__ void upmod_kernel(const float* __restrict__ x)
{
    const int plane = blockIdx.x;         // b*CIN + ci
    __shared__ float xt[HI * WI];
    const float* xp = x + (size_t)plane * (HI * WI);
    for (int i = threadIdx.x; i < HI * WI; i += blockDim.x)
        xt[i] = xp[i];
    __syncthreads();

    const float s = g_s[plane];
    float* dst = g_xm + (size_t)plane * PLANE;

    for (int idx = threadIdx.x; idx < PLANE; idx += blockDim.x) {
        const int r = idx / PADW;
        const int c = idx - r * PADW;
        float v = 0.f;
        if (r > 0 && r < PADW - 1 && c > 0 && c < PADW - 1) {
            const int oy = r - 1, ox = c - 1;
            const int my = oy >> 1, mx = ox >> 1;
            int iy0, iy1, ix0, ix1;
            float wy0, wx0;
            // half-pixel centers: src = 0.5*o - 0.25
            if (oy & 1) { iy0 = my; iy1 = min(my + 1, HI - 1); wy0 = 0.75f; }
            else        { iy0 = max(my - 1, 0); iy1 = my;      wy0 = 0.25f; }
            if (ox & 1) { ix0 = mx; ix1 = min(mx + 1, WI - 1); wx0 = 0.75f; }
            else        { ix0 = max(mx - 1, 0); ix1 = mx;      wx0 = 0.25f; }
            const float wy1 = 1.f - wy0, wx1 = 1.f - wx0;
            const float v00 = xt[iy0 * WI + ix0], v01 = xt[iy0 * WI + ix1];
            const float v10 = xt[iy1 * WI + ix0], v11 = xt[iy1 * WI + ix1];
            v = (wy0 * (wx0 * v00 + wx1 * v01) +
                 wy1 * (wx0 * v10 + wx1 * v11)) * s;
        }
        dst[idx] = v;
    }
}

// ---------------- kernel 5: conv (9 taps x GEMM) + fused epilogue ----------
#define TM 128
#define TN 128
#define BK 8
#define NITER (9 * (CIN / BK))   // 576

__global__ __launch_bounds__(256, 2)
void conv_kernel(const float* __restrict__ noise,
                 const float* __restrict__ nw_p,
                 float* __restrict__ out)
{
    const int cout0 = blockIdx.x * TM;    // 4 blocks
    const int oy0   = blockIdx.y * 2;     // 32 row pairs
    const int b     = blockIdx.z;         // 16

    __shared__ float As[2][BK][TM];
    __shared__ float Bs[2][BK][TN];

    const int t = threadIdx.x;
    // A-tile load mapping: thread -> (row m, 4 k's)
    const int am = t >> 1;
    const int ak = (t & 1) * 4;
    // B-tile load mapping: thread -> (k, 4 n's)
    const int bk = t >> 5;
    const int bn = (t & 31) * 4;
    const int brow = bn >> 6;             // which of the 2 output rows
    const int bcol = bn & 63;
    // compute mapping
    const int ty = t >> 4;                // 16 -> 8 couts each
    const int tx = t & 15;                // 16 -> 8 pixels each

    const float* xbase = g_xm + (size_t)b * CIN * PLANE;

    float acc[8][8];
#pragma unroll
    for (int i = 0; i < 8; ++i)
#pragma unroll
        for (int j = 0; j < 8; ++j)
            acc[i][j] = 0.f;

    // prologue: tile 0 (tap 0 -> ky=0,kx=0; ci0=0)
    {
        const float4 av = *(const float4*)(g_wt + (size_t)(cout0 + am) * CIN + ak);
        As[0][ak + 0][am] = av.x; As[0][ak + 1][am] = av.y;
        As[0][ak + 2][am] = av.z; As[0][ak + 3][am] = av.w;
        const float* bp = xbase + (size_t)bk * PLANE + (size_t)(oy0 + brow) * PADW + bcol;
        const float4 bv = make_float4(bp[0], bp[1], bp[2], bp[3]);
        *(float4*)&Bs[0][bk][bn] = bv;
    }
    __syncthreads();

    int buf = 0;
    for (int it = 0; it < NITER; ++it) {
        float4 av, bv;
        const bool has_next = (it + 1) < NITER;
        if (has_next) {
            const int nit = it + 1;
            const int kk  = nit >> 6;            // tap index (64 ci-chunks per tap)
            const int ci0 = (nit & 63) << 3;
            const int ky  = kk / 3;
            const int kx  = kk - ky * 3;
            av = *(const float4*)(g_wt + (size_t)kk * COUT * CIN
                                  + (size_t)(cout0 + am) * CIN + ci0 + ak);
            const float* bp = xbase + (size_t)(ci0 + bk) * PLANE
                              + (size_t)(oy0 + brow + ky) * PADW + (bcol + kx);
            bv = make_float4(bp[0], bp[1], bp[2], bp[3]);
        }

#pragma unroll
        for (int k = 0; k < BK; ++k) {
            const float4 a0 = *(const float4*)&As[buf][k][ty * 8];
            const float4 a1 = *(const float4*)&As[buf][k][ty * 8 + 4];
            const float4 b0 = *(const float4*)&Bs[buf][k][tx * 8];
            const float4 b1 = *(const float4*)&Bs[buf][k][tx * 8 + 4];

            acc[0][0] = fmaf(a0.x, b0.x, acc[0][0]);
            acc[0][1] = fmaf(a0.x, b0.y, acc[0][1]);
            acc[0][2] = fmaf(a0.x, b0.z, acc[0][2]);
            acc[0][3] = fmaf(a0.x, b0.w, acc[0][3]);
            acc[0][4] = fmaf(a0.x, b1.x, acc[0][4]);
            acc[0][5] = fmaf(a0.x, b1.y, acc[0][5]);
            acc[0][6] = fmaf(a0.x, b1.z, acc[0][6]);
            acc[0][7] = fmaf(a0.x, b1.w, acc[0][7]);

            acc[1][0] = fmaf(a0.y, b0.x, acc[1][0]);
            acc[1][1] = fmaf(a0.y, b0.y, acc[1][1]);
            acc[1][2] = fmaf(a0.y, b0.z, acc[1][2]);
            acc[1][3] = fmaf(a0.y, b0.w, acc[1][3]);
            acc[1][4] = fmaf(a0.y, b1.x, acc[1][4]);
            acc[1][5] = fmaf(a0.y, b1.y, acc[1][5]);
            acc[1][6] = fmaf(a0.y, b1.z, acc[1][6]);
            acc[1][7] = fmaf(a0.y, b1.w, acc[1][7]);

            acc[2][0] = fmaf(a0.z, b0.x, acc[2][0]);
            acc[2][1] = fmaf(a0.z, b0.y, acc[2][1]);
            acc[2][2] = fmaf(a0.z, b0.z, acc[2][2]);
            acc[2][3] = fmaf(a0.z, b0.w, acc[2][3]);
            acc[2][4] = fmaf(a0.z, b1.x, acc[2][4]);
            acc[2][5] = fmaf(a0.z, b1.y, acc[2][5]);
            acc[2][6] = fmaf(a0.z, b1.z, acc[2][6]);
            acc[2][7] = fmaf(a0.z, b1.w, acc[2][7]);

            acc[3][0] = fmaf(a0.w, b0.x, acc[3][0]);
            acc[3][1] = fmaf(a0.w, b0.y, acc[3][1]);
            acc[3][2] = fmaf(a0.w, b0.z, acc[3][2]);
            acc[3][3] = fmaf(a0.w, b0.w, acc[3][3]);
            acc[3][4] = fmaf(a0.w, b1.x, acc[3][4]);
            acc[3][5] = fmaf(a0.w, b1.y, acc[3][5]);
            acc[3][6] = fmaf(a0.w, b1.z, acc[3][6]);
            acc[3][7] = fmaf(a0.w, b1.w, acc[3][7]);

            acc[4][0] = fmaf(a1.x, b0.x, acc[4][0]);
            acc[4][1] = fmaf(a1.x, b0.y, acc[4][1]);
            acc[4][2] = fmaf(a1.x, b0.z, acc[4][2]);
            acc[4][3] = fmaf(a1.x, b0.w, acc[4][3]);
            acc[4][4] = fmaf(a1.x, b1.x, acc[4][4]);
            acc[4][5] = fmaf(a1.x, b1.y, acc[4][5]);
            acc[4][6] = fmaf(a1.x, b1.z, acc[4][6]);
            acc[4][7] = fmaf(a1.x, b1.w, acc[4][7]);

            acc[5][0] = fmaf(a1.y, b0.x, acc[5][0]);
            acc[5][1] = fmaf(a1.y, b0.y, acc[5][1]);
            acc[5][2] = fmaf(a1.y, b0.z, acc[5][2]);
            acc[5][3] = fmaf(a1.y, b0.w, acc[5][3]);
            acc[5][4] = fmaf(a1.y, b1.x, acc[5][4]);
            acc[5][5] = fmaf(a1.y, b1.y, acc[5][5]);
            acc[5][6] = fmaf(a1.y, b1.z, acc[5][6]);
            acc[5][7] = fmaf(a1.y, b1.w, acc[5][7]);

            acc[6][0] = fmaf(a1.z, b0.x, acc[6][0]);
            acc[6][1] = fmaf(a1.z, b0.y, acc[6][1]);
            acc[6][2] = fmaf(a1.z, b0.z, acc[6][2]);
            acc[6][3] = fmaf(a1.z, b0.w, acc[6][3]);
            acc[6][4] = fmaf(a1.z, b1.x, acc[6][4]);
            acc[6][5] = fmaf(a1.z, b1.y, acc[6][5]);
            acc[6][6] = fmaf(a1.z, b1.z, acc[6][6]);
            acc[6][7] = fmaf(a1.z, b1.w, acc[6][7]);

            acc[7][0] = fmaf(a1.w, b0.x, acc[7][0]);
            acc[7][1] = fmaf(a1.w, b0.y, acc[7][1]);
            acc[7][2] = fmaf(a1.w, b0.z, acc[7][2]);
            acc[7][3] = fmaf(a1.w, b0.w, acc[7][3]);
            acc[7][4] = fmaf(a1.w, b1.x, acc[7][4]);
            acc[7][5] = fmaf(a1.w, b1.y, acc[7][5]);
            acc[7][6] = fmaf(a1.w, b1.z, acc[7][6]);
            acc[7][7] = fmaf(a1.w, b1.w, acc[7][7]);
        }

        if (has_next) {
            const int nb = buf ^ 1;
            As[nb][ak + 0][am] = av.x; As[nb][ak + 1][am] = av.y;
            As[nb][ak + 2][am] = av.z; As[nb][ak + 3][am] = av.w;
            *(float4*)&Bs[nb][bk][bn] = bv;
            __syncthreads();
            buf = nb;
        }
    }

    // fused epilogue: demod, noise, leaky relu, gain
    const float nw = nw_p[0];
    float dmod[8];
#pragma unroll
    for (int i = 0; i < 8; ++i)
        dmod[i] = g_demod[b * COUT + cout0 + ty * 8 + i];

#pragma unroll
    for (int j = 0; j < 8; ++j) {
        const int n   = tx * 8 + j;
        const int row = oy0 + (n >> 6);
        const int col = n & 63;
        const float nz = nw * noise[((size_t)b * HO + row) * WO + col];
#pragma unroll
        for (int i = 0; i < 8; ++i) {
            const int o = cout0 + ty * 8 + i;
            float v = acc[i][j] * dmod[i] + nz;
            v = (v >= 0.f) ? v : NEG_SLOPE * v;
            out[(((size_t)b * COUT + o) * HO + row) * WO + col] = v * ACT_GAIN;
        }
    }
}

// ---------------- launch ----------------------------------------------------
extern "C" void kernel_launch(void* const* d_in, const int* in_sizes, int n_in,
                              void* d_out, int out_size)
{
    const float* x      = (const float*)d_in[0];
    const float* w      = (const float*)d_in[1];
    const float* noise  = (const float*)d_in[2];
    const float* lin_w  = (const float*)d_in[3];
    const float* lin_b  = (const float*)d_in[4];
    const float* conv_w = (const float*)d_in[5];
    const float* nw     = (const float*)d_in[6];
    float* out = (float*)d_out;

    style_kernel<<<BB, SDIM>>>(w, lin_w, lin_b);
    wprep_kernel<<<COUT, CIN>>>(conv_w);
    demod_kernel<<<BB, COUT>>>();
    upmod_kernel<<<BB * CIN, 256>>>(x);

    dim3 grid(COUT / TM, HO / 2, BB);
    conv_kernel<<<grid, 256>>>(noise, nw, out);
}

// round 5
// speedup vs baseline: 3.6704x; 3.6704x over previous
#include <cuda_runtime.h>
#include <cstdint>

// ---------------- problem constants ----------------
#define BB    16
#define CIN   512
#define COUT  512
#define SDIM  512
#define HI    32
#define WI    32
#define HO    64
#define WO    64
#define PADW  66
#define KTOT  (9 * CIN)          // 4608

#define LIN_SCALE  0.04419417382415922f
#define CONV_SCALE 0.014731391274719742f
#define ACT_GAIN   1.4142135623730951f
#define NEG_SLOPE  0.2f
#define EPS_DEMOD  1e-8f

// ---------------- device scratch ----------------
__device__ float g_s[BB * CIN];
__device__ float g_demod[BB * COUT];
__device__ float g_wt[(size_t)COUT * KTOT];             // tf32-rounded, [cout][tap*512+ci]
__device__ float g_wsq[COUT * CIN];
__device__ float g_xt[(size_t)BB * HI * WI * CIN];      // channel-last input
__device__ float g_xm[(size_t)BB * PADW * PADW * CIN];  // tf32-rounded padded upsample

// ---------------- helpers ----------------
__device__ __forceinline__ float to_tf32(float x) {
    uint32_t r;
    asm("cvt.rna.tf32.f32 %0, %1;" : "=r"(r) : "f"(x));
    return __uint_as_float(r);
}
__device__ __forceinline__ uint32_t smem_u32(const void* p) {
    uint32_t a;
    asm("{ .reg .u64 t; cvta.to.shared.u64 t, %1; cvt.u32.u64 %0, t; }"
        : "=r"(a) : "l"(p));
    return a;
}
__device__ __forceinline__ void cpasync16(uint32_t dst, const void* src) {
    asm volatile("cp.async.cg.shared.global [%0], [%1], 16;"
                 :: "r"(dst), "l"(src) : "memory");
}
__device__ __forceinline__ void cp_commit() {
    asm volatile("cp.async.commit_group;" ::: "memory");
}
template<int N> __device__ __forceinline__ void cp_wait() {
    asm volatile("cp.async.wait_group %0;" :: "n"(N) : "memory");
}
__device__ __forceinline__ void mma_tf32(float* c, const uint32_t* a,
                                         uint32_t b0, uint32_t b1) {
    asm volatile(
        "mma.sync.aligned.m16n8k8.row.col.f32.tf32.tf32.f32 "
        "{%0,%1,%2,%3}, {%4,%5,%6,%7}, {%8,%9}, {%0,%1,%2,%3};"
        : "+f"(c[0]), "+f"(c[1]), "+f"(c[2]), "+f"(c[3])
        : "r"(a[0]), "r"(a[1]), "r"(a[2]), "r"(a[3]), "r"(b0), "r"(b1));
}

// ---------------- kernel 1: style ----------------
__global__ void style_kernel(const float* __restrict__ w,
                             const float* __restrict__ lin_w,
                             const float* __restrict__ lin_b)
{
    const int b = blockIdx.x, i = threadIdx.x;
    __shared__ float ws[SDIM];
    ws[i] = w[b * SDIM + i];
    __syncthreads();
    const float* lw = lin_w + (size_t)i * SDIM;
    float acc = 0.f;
#pragma unroll 8
    for (int j = 0; j < SDIM; ++j) acc = fmaf(ws[j], lw[j], acc);
    g_s[b * CIN + i] = acc * LIN_SCALE + lin_b[i];
}

// ---------------- kernel 2: weight K-major (tf32) + sum-of-squares ---------
__global__ void wprep_kernel(const float* __restrict__ conv_w)
{
    const int o = blockIdx.x, i = threadIdx.x;
    const float* wp = conv_w + ((size_t)o * CIN + i) * 9;
    float q = 0.f;
#pragma unroll
    for (int kk = 0; kk < 9; ++kk) {
        const float v = wp[kk] * CONV_SCALE;
        g_wt[(size_t)o * KTOT + kk * CIN + i] = to_tf32(v);
        q = fmaf(v, v, q);   // exact fp32 for demod
    }
    g_wsq[o * CIN + i] = q;
}

// ---------------- kernel 3: demod ----------------
__global__ void demod_kernel()
{
    const int b = blockIdx.x, o = threadIdx.x;
    __shared__ float s2[CIN];
    const float sv = g_s[b * CIN + o];
    s2[o] = sv * sv;
    __syncthreads();
    const float* wq = g_wsq + (size_t)o * CIN;
    float acc = 0.f;
#pragma unroll 8
    for (int i = 0; i < CIN; ++i) acc = fmaf(wq[i], s2[i], acc);
    g_demod[b * COUT + o] = rsqrtf(acc + EPS_DEMOD);
}

// ---------------- kernel 4a: transpose x to channel-last ----------------
__global__ void transpose_kernel(const float* __restrict__ x)
{
    __shared__ float tile[32][33];
    const int b = blockIdx.z, p0 = blockIdx.x * 32, c0 = blockIdx.y * 32;
    const int tx = threadIdx.x, ty = threadIdx.y;     // (32, 8)
    for (int i = ty; i < 32; i += 8)
        tile[i][tx] = x[((size_t)(b * CIN) + c0 + i) * (HI * WI) + p0 + tx];
    __syncthreads();
    for (int i = ty; i < 32; i += 8)
        g_xt[((size_t)(b * HI * WI) + p0 + i) * CIN + c0 + tx] = tile[tx][i];
}

// ---------------- kernel 4b: upsample*style, channel-last, zero halo, tf32 -
__global__ void upmod_cl_kernel()
{
    const int r = blockIdx.x;         // 0..65
    const int b = blockIdx.y;
    const int ci = threadIdx.x;       // 512
    float* dst = g_xm + ((size_t)(b * PADW + r) * PADW) * CIN + ci;
    if (r == 0 || r == PADW - 1) {
        for (int c = 0; c < PADW; ++c) dst[(size_t)c * CIN] = 0.f;
        return;
    }
    const int oy = r - 1, my = oy >> 1;
    int iy0, iy1; float wy0;
    if (oy & 1) { iy0 = my; iy1 = min(my + 1, HI - 1); wy0 = 0.75f; }
    else        { iy0 = max(my - 1, 0); iy1 = my;      wy0 = 0.25f; }
    const float wy1 = 1.f - wy0;
    const float s = g_s[b * CIN + ci];
    const float* xb = g_xt + (size_t)b * HI * WI * CIN + ci;
    dst[0] = 0.f;
    dst[(size_t)(PADW - 1) * CIN] = 0.f;
    for (int c = 1; c < PADW - 1; ++c) {
        const int ox = c - 1, mx = ox >> 1;
        int ix0, ix1; float wx0;
        if (ox & 1) { ix0 = mx; ix1 = min(mx + 1, WI - 1); wx0 = 0.75f; }
        else        { ix0 = max(mx - 1, 0); ix1 = mx;      wx0 = 0.25f; }
        const float wx1 = 1.f - wx0;
        const float v00 = xb[(size_t)(iy0 * WI + ix0) * CIN];
        const float v01 = xb[(size_t)(iy0 * WI + ix1) * CIN];
        const float v10 = xb[(size_t)(iy1 * WI + ix0) * CIN];
        const float v11 = xb[(size_t)(iy1 * WI + ix1) * CIN];
        dst[(size_t)c * CIN] = to_tf32(
            (wy0 * (wx0 * v00 + wx1 * v01) + wy1 * (wx0 * v10 + wx1 * v11)) * s);
    }
}

// ---------------- kernel 5: mma.sync tf32 conv + fused epilogue ------------
// CTA tile: M=128 (cout) x N=256 (pixels) x K-chunk 32; 144 chunks.
// 8 warps 2x4, warp tile 64x64. Smem row stride 36 floats (conflict-free frags).
#define ASTRIDE 36
#define A_ELEMS (128 * ASTRIDE)          // 4608 floats
#define B_ELEMS (256 * ASTRIDE)          // 9216 floats
#define BUF_ELEMS (A_ELEMS + B_ELEMS)    // 13824
#define A_BYTES (A_ELEMS * 4)
#define BUF_BYTES (BUF_ELEMS * 4)        // 55296
#define CONV_SMEM (2 * BUF_BYTES)        // 110592
#define NCHUNK 144

__global__ __launch_bounds__(256)
void conv_mma_kernel(const float* __restrict__ noise,
                     const float* __restrict__ nw_p,
                     float* __restrict__ out)
{
    extern __shared__ float sm[];
    const uint32_t sbase = smem_u32(sm);

    const int t = threadIdx.x;
    const int wid = t >> 5, lane = t & 31;
    const int g = lane >> 2, tg = lane & 3;
    const int wm = wid >> 2, wn = wid & 3;

    const int cout0 = blockIdx.x * 128;
    const int py4   = blockIdx.y * 4;
    const int b     = blockIdx.z;

    const float* xmb = g_xm + (size_t)b * PADW * PADW * CIN;
    const int f4i = t & 7;     // 16B segment within 32-float k-chunk
    const int row0 = t >> 3;   // 0..31

    auto stage = [&](int it, int buf) {
        const int tap = it >> 4;
        const int ci0 = (it & 15) << 5;
        const int ky = tap / 3, kx = tap - 3 * ky;
        const uint32_t abase = sbase + buf * BUF_BYTES;
        const float* wsrc = g_wt + (size_t)cout0 * KTOT + tap * CIN + ci0 + f4i * 4;
#pragma unroll
        for (int j = 0; j < 4; ++j) {
            const int row = row0 + 32 * j;
            cpasync16(abase + (uint32_t)(row * ASTRIDE + f4i * 4) * 4,
                      wsrc + (size_t)row * KTOT);
        }
        const uint32_t bbase = abase + A_BYTES;
#pragma unroll
        for (int j = 0; j < 8; ++j) {
            const int n = row0 + 32 * j;
            const int r = py4 + (n >> 6) + ky;
            const int c = (n & 63) + kx;
            cpasync16(bbase + (uint32_t)(n * ASTRIDE + f4i * 4) * 4,
                      xmb + ((size_t)r * PADW + c) * CIN + ci0 + f4i * 4);
        }
        cp_commit();
    };

    float acc[4][8][4];
#pragma unroll
    for (int mt = 0; mt < 4; ++mt)
#pragma unroll
        for (int nt = 0; nt < 8; ++nt)
#pragma unroll
            for (int q = 0; q < 4; ++q) acc[mt][nt][q] = 0.f;

    stage(0, 0);
    stage(1, 1);

    for (int it = 0; it < NCHUNK; ++it) {
        if (it + 1 < NCHUNK) cp_wait<1>(); else cp_wait<0>();
        __syncthreads();

        const float* A = sm + (it & 1) * BUF_ELEMS;
        const float* B = A + A_ELEMS;

#pragma unroll
        for (int k8 = 0; k8 < 4; ++k8) {
            const int ka = k8 * 8 + tg;
            uint32_t a[4][4];
#pragma unroll
            for (int mt = 0; mt < 4; ++mt) {
                const int mb = wm * 64 + mt * 16;
                a[mt][0] = __float_as_uint(A[(mb + g) * ASTRIDE + ka]);
                a[mt][1] = __float_as_uint(A[(mb + g + 8) * ASTRIDE + ka]);
                a[mt][2] = __float_as_uint(A[(mb + g) * ASTRIDE + ka + 4]);
                a[mt][3] = __float_as_uint(A[(mb + g + 8) * ASTRIDE + ka + 4]);
            }
#pragma unroll
            for (int nt = 0; nt < 8; ++nt) {
                const int nb = wn * 64 + nt * 8;
                const uint32_t b0 = __float_as_uint(B[(nb + g) * ASTRIDE + ka]);
                const uint32_t b1 = __float_as_uint(B[(nb + g) * ASTRIDE + ka + 4]);
#pragma unroll
                for (int mt = 0; mt < 4; ++mt)
                    mma_tf32(acc[mt][nt], a[mt], b0, b1);
            }
        }

        __syncthreads();
        if (it + 2 < NCHUNK) stage(it + 2, it & 1);
    }

    // fused epilogue: demod, noise, leaky relu, gain
    const float nwv = nw_p[0];
#pragma unroll
    for (int mt = 0; mt < 4; ++mt) {
        const int m0 = cout0 + wm * 64 + mt * 16 + g;
        const float dm0 = g_demod[b * COUT + m0];
        const float dm1 = g_demod[b * COUT + m0 + 8];
#pragma unroll
        for (int nt = 0; nt < 8; ++nt) {
            const int n = wn * 64 + nt * 8 + tg * 2;
            const int row = py4 + (n >> 6);
            const int col = n & 63;
            const float* nz = noise + ((size_t)b * HO + row) * WO + col;
            const float n0 = nwv * nz[0], n1 = nwv * nz[1];
            float* o0 = out + (((size_t)(b * COUT + m0)) * HO + row) * WO + col;
            float* o1 = o0 + (size_t)8 * HO * WO;
            float v;
            float2 r0, r1;
            v = acc[mt][nt][0] * dm0 + n0; r0.x = ((v >= 0.f) ? v : NEG_SLOPE * v) * ACT_GAIN;
            v = acc[mt][nt][1] * dm0 + n1; r0.y = ((v >= 0.f) ? v : NEG_SLOPE * v) * ACT_GAIN;
            v = acc[mt][nt][2] * dm1 + n0; r1.x = ((v >= 0.f) ? v : NEG_SLOPE * v) * ACT_GAIN;
            v = acc[mt][nt][3] * dm1 + n1; r1.y = ((v >= 0.f) ? v : NEG_SLOPE * v) * ACT_GAIN;
            *(float2*)o0 = r0;
            *(float2*)o1 = r1;
        }
    }
}

// ---------------- launch ----------------
extern "C" void kernel_launch(void* const* d_in, const int* in_sizes, int n_in,
                              void* d_out, int out_size)
{
    const float* x      = (const float*)d_in[0];
    const float* w      = (const float*)d_in[1];
    const float* noise  = (const float*)d_in[2];
    const float* lin_w  = (const float*)d_in[3];
    const float* lin_b  = (const float*)d_in[4];
    const float* conv_w = (const float*)d_in[5];
    const float* nw     = (const float*)d_in[6];
    float* out = (float*)d_out;

    cudaFuncSetAttribute(conv_mma_kernel,
                         cudaFuncAttributeMaxDynamicSharedMemorySize, CONV_SMEM);

    style_kernel<<<BB, SDIM>>>(w, lin_w, lin_b);
    wprep_kernel<<<COUT, CIN>>>(conv_w);
    demod_kernel<<<BB, COUT>>>();
    transpose_kernel<<<dim3(32, 16, 16), dim3(32, 8)>>>(x);
    upmod_cl_kernel<<<dim3(PADW, BB), CIN>>>();

    dim3 grid(COUT / 128, (HO * WO) / 256, BB);
    conv_mma_kernel<<<grid, 256, CONV_SMEM>>>(noise, nw, out);
}